// round 1
// baseline (speedup 1.0000x reference)
#include <cuda_runtime.h>

#define N_PTS 32768
#define M_PTS 8192
#define CIN   64
#define COUT  128
#define KNN_K 16

#define FPS_CTAS    64
#define FPS_THREADS 256
// 64*256 = 16384 threads, 2 points per thread -> 32768 points, fully register-resident

// ---------------- scratch (device globals; no allocation allowed) ----------------
__device__ unsigned long long g_slot[2][FPS_CTAS];   // zero-initialized; reset at kernel end
__device__ int   g_fps_idx[M_PTS];
__device__ int   g_nbr[M_PTS * KNN_K];
__device__ float g_h[N_PTS * COUT];                  // relu(xW+b), 16 MB

// strict non-FMA fp32 distance: matches XLA's mul -> reduce-add lowering
__device__ __forceinline__ float dist2s(float x, float y, float z,
                                        float px, float py, float pz) {
    float dx = __fsub_rn(x, px);
    float dy = __fsub_rn(y, py);
    float dz = __fsub_rn(z, pz);
    return __fadd_rn(__fadd_rn(__fmul_rn(dx, dx), __fmul_rn(dy, dy)), __fmul_rn(dz, dz));
}

// ---------------- FPS: persistent multi-CTA with flat slot exchange ----------------
// key layout: [63:32] = float bits of min-dist (>=0, order-preserving as unsigned)
//             [31:17] = 32767 - point_idx  (so max-reduce breaks ties toward SMALLER idx,
//                       matching jnp.argmax first-index semantics)
//             [16:14] = 0
//             [13:0]  = iteration tag (it <= 8191, fits)
__global__ void __launch_bounds__(FPS_THREADS) fps_kernel(const float* __restrict__ pos) {
    const int tid  = threadIdx.x;
    const int cta  = blockIdx.x;
    const int gtid = cta * FPS_THREADS + tid;
    const int i0 = gtid * 2, i1 = i0 + 1;

    const float x0 = pos[i0 * 3 + 0], y0 = pos[i0 * 3 + 1], z0 = pos[i0 * 3 + 2];
    const float x1 = pos[i1 * 3 + 0], y1 = pos[i1 * 3 + 1], z1 = pos[i1 * 3 + 2];
    float m0 = __int_as_float(0x7f800000);  // +inf
    float m1 = m0;

    __shared__ unsigned long long s_red[FPS_THREADS / 32];
    __shared__ float s_px, s_py, s_pz;

    float px = pos[0], py = pos[1], pz = pos[2];   // first pick = index 0
    if (cta == 0 && tid == 0) g_fps_idx[0] = 0;

    volatile unsigned long long* slots = (volatile unsigned long long*)&g_slot[0][0];

    for (int it = 1; it < M_PTS; ++it) {
        // update min-dist (min is exact; order-independent)
        m0 = fminf(m0, dist2s(x0, y0, z0, px, py, pz));
        m1 = fminf(m1, dist2s(x1, y1, z1, px, py, pz));

        unsigned long long k0 = ((unsigned long long)__float_as_uint(m0) << 32)
                              | ((unsigned long long)(32767 - i0) << 17);
        unsigned long long k1 = ((unsigned long long)__float_as_uint(m1) << 32)
                              | ((unsigned long long)(32767 - i1) << 17);
        unsigned long long k = (k0 > k1) ? k0 : k1;

        #pragma unroll
        for (int off = 16; off > 0; off >>= 1) {
            unsigned long long o = __shfl_down_sync(0xffffffffu, k, off);
            if (o > k) k = o;
        }
        if ((tid & 31) == 0) s_red[tid >> 5] = k;
        __syncthreads();

        if (tid < 32) {
            // reduce the 8 warp candidates (lanes 0..7 hold data)
            unsigned long long kk = (tid < FPS_THREADS / 32) ? s_red[tid] : 0ull;
            #pragma unroll
            for (int off = 4; off > 0; off >>= 1) {
                unsigned long long o = __shfl_down_sync(0xffffffffu, kk, off);
                if (o > kk) kk = o;
            }
            const unsigned int tag = (unsigned int)(it & 0x3FFF);
            const int par = (it & 1) * FPS_CTAS;
            if (tid == 0) slots[par + cta] = kk | (unsigned long long)tag;

            // every CTA polls all 64 slots (double-buffered -> no overwrite race)
            unsigned long long best = 0ull;
            #pragma unroll
            for (int s = 0; s < FPS_CTAS / 32; ++s) {
                unsigned long long v;
                do {
                    v = slots[par + tid + s * 32];
                } while ((unsigned int)(v & 0x3FFFull) != tag);
                if (v > best) best = v;
            }
            #pragma unroll
            for (int off = 16; off > 0; off >>= 1) {
                unsigned long long o = __shfl_down_sync(0xffffffffu, best, off);
                if (o > best) best = o;
            }
            if (tid == 0) {
                int idx = 32767 - (int)((best >> 17) & 0x7FFF);
                if (cta == 0) g_fps_idx[it] = idx;
                s_px = pos[idx * 3 + 0];
                s_py = pos[idx * 3 + 1];
                s_pz = pos[idx * 3 + 2];
            }
        }
        __syncthreads();
        px = s_px; py = s_py; pz = s_pz;
    }

    // reset slots so the next graph replay starts clean (tag 0 is never polled)
    if (tid == 0) {
        ((volatile unsigned long long*)g_slot)[cta] = 0ull;
        ((volatile unsigned long long*)g_slot)[FPS_CTAS + cta] = 0ull;
    }
}

// ---------------- KNN: warp per query, smem-chunked candidate points ----------------
#define KNN_THREADS 256
#define KNN_CHUNK   4096   // 4096 * 3 * 4B = 48 KB smem

__global__ void __launch_bounds__(KNN_THREADS) knn_kernel(const float* __restrict__ pos) {
    __shared__ float s_pos[KNN_CHUNK * 3];
    const int tid  = threadIdx.x;
    const int warp = tid >> 5, lane = tid & 31;
    const int m    = blockIdx.x * (KNN_THREADS / 32) + warp;

    const int qidx = g_fps_idx[m];
    const float qx = pos[qidx * 3 + 0];
    const float qy = pos[qidx * 3 + 1];
    const float qz = pos[qidx * 3 + 2];

    unsigned long long bk[KNN_K];
    #pragma unroll
    for (int i = 0; i < KNN_K; ++i) bk[i] = 0xFFFFFFFFFFFFFFFFull;
    unsigned long long worst = 0xFFFFFFFFFFFFFFFFull;
    int ws = 0;

    for (int base = 0; base < N_PTS; base += KNN_CHUNK) {
        __syncthreads();
        for (int i = tid; i < KNN_CHUNK * 3; i += KNN_THREADS)
            s_pos[i] = pos[base * 3 + i];
        __syncthreads();

        for (int j = lane; j < KNN_CHUNK; j += 32) {
            float d = dist2s(qx, qy, qz, s_pos[j * 3], s_pos[j * 3 + 1], s_pos[j * 3 + 2]);
            unsigned long long key = ((unsigned long long)__float_as_uint(d) << 32)
                                   | (unsigned int)(base + j);
            if (key < worst) {          // lexicographic (d, idx): matches stable top_k
                bk[ws] = key;
                worst = 0ull;
                #pragma unroll
                for (int i = 0; i < KNN_K; ++i)
                    if (bk[i] > worst) { worst = bk[i]; ws = i; }
            }
        }
    }

    // merge 32 lanes' top-16 -> global top-16 (keys are unique: idx in low bits)
    for (int r = 0; r < KNN_K; ++r) {
        unsigned long long lm = 0xFFFFFFFFFFFFFFFFull;
        #pragma unroll
        for (int i = 0; i < KNN_K; ++i) if (bk[i] < lm) lm = bk[i];
        unsigned long long w = lm;
        #pragma unroll
        for (int off = 16; off > 0; off >>= 1) {
            unsigned long long o = __shfl_xor_sync(0xffffffffu, w, off);
            if (o < w) w = o;
        }
        if (lane == 0) g_nbr[m * KNN_K + r] = (int)(w & 0xFFFFFFFFull);
        if (lm == w) {
            bool rm = false;
            #pragma unroll
            for (int i = 0; i < KNN_K; ++i)
                if (!rm && bk[i] == w) { bk[i] = 0xFFFFFFFFFFFFFFFFull; rm = true; }
        }
    }
}

// ---------------- MLP: h = relu(x @ W + b), smem-tiled fp32 ----------------
#define GEMM_THREADS 256
#define GEMM_ROWS    16

__global__ void __launch_bounds__(GEMM_THREADS) mlp_kernel(const float* __restrict__ x,
                                                           const float* __restrict__ W,
                                                           const float* __restrict__ b) {
    __shared__ float sW[CIN * COUT];        // 32 KB
    __shared__ float sx[GEMM_ROWS * CIN];   // 4 KB
    const int tid  = threadIdx.x;
    const int row0 = blockIdx.x * GEMM_ROWS;

    for (int i = tid; i < CIN * COUT; i += GEMM_THREADS) sW[i] = W[i];
    for (int i = tid; i < GEMM_ROWS * CIN; i += GEMM_THREADS) sx[i] = x[row0 * CIN + i];
    __syncthreads();

    const int c  = tid & (COUT - 1);
    const int rg = tid >> 7;   // 0 or 1 -> rows rg*8 .. rg*8+7
    float acc[8];
    #pragma unroll
    for (int r = 0; r < 8; ++r) acc[r] = 0.f;

    for (int k = 0; k < CIN; ++k) {
        float wv = sW[k * COUT + c];
        #pragma unroll
        for (int r = 0; r < 8; ++r)
            acc[r] = fmaf(sx[(rg * 8 + r) * CIN + k], wv, acc[r]);
    }
    float bv = b[c];
    #pragma unroll
    for (int r = 0; r < 8; ++r)
        g_h[(row0 + rg * 8 + r) * COUT + c] = fmaxf(acc[r] + bv, 0.f);
}

// ---------------- max over K neighbors ----------------
__global__ void __launch_bounds__(COUT) gather_kernel(float* __restrict__ out) {
    const int m = blockIdx.x;
    const int c = threadIdx.x;
    __shared__ int s_n[KNN_K];
    if (c < KNN_K) s_n[c] = g_nbr[m * KNN_K + c];
    __syncthreads();
    float best = g_h[s_n[0] * COUT + c];
    #pragma unroll
    for (int k = 1; k < KNN_K; ++k)
        best = fmaxf(best, g_h[s_n[k] * COUT + c]);
    out[m * COUT + c] = best;
}

// ---------------- sub_pos + sub_batch outputs ----------------
__global__ void subpos_kernel(const float* __restrict__ pos, float* __restrict__ out) {
    const int m = blockIdx.x * blockDim.x + threadIdx.x;
    if (m < M_PTS) {
        const int idx = g_fps_idx[m];
        float* sp = out + (M_PTS * COUT);            // sub_pos after out
        sp[m * 3 + 0] = pos[idx * 3 + 0];
        sp[m * 3 + 1] = pos[idx * 3 + 1];
        sp[m * 3 + 2] = pos[idx * 3 + 2];
        out[M_PTS * COUT + M_PTS * 3 + m] = 0.0f;    // sub_batch = 0 (bit-identical to int32 0)
    }
}

extern "C" void kernel_launch(void* const* d_in, const int* in_sizes, int n_in,
                              void* d_out, int out_size) {
    const float* x   = (const float*)d_in[0];
    const float* pos = (const float*)d_in[1];
    // d_in[2] = batch (all zeros, unused)
    const float* W   = (const float*)d_in[3];
    const float* b   = (const float*)d_in[4];
    float* out = (float*)d_out;

    mlp_kernel<<<N_PTS / GEMM_ROWS, GEMM_THREADS>>>(x, W, b);
    fps_kernel<<<FPS_CTAS, FPS_THREADS>>>(pos);
    subpos_kernel<<<(M_PTS + 255) / 256, 256>>>(pos, out);
    knn_kernel<<<M_PTS / (KNN_THREADS / 32), KNN_THREADS>>>(pos);
    gather_kernel<<<M_PTS, COUT>>>(out);
}

// round 2
// speedup vs baseline: 3.2580x; 3.2580x over previous
#include <cuda_runtime.h>
#include <cstdint>

#define N_PTS 32768
#define M_PTS 8192
#define CIN   64
#define COUT  128
#define KNN_K 16

// ---------------- FPS config: one 8-CTA cluster, DSMEM exchange ----------------
#define FPS_CTAS    8
#define FPS_THREADS 1024
#define FPS_PPT     4      // points per thread: 8*1024*4 = 32768

// ---------------- scratch (device globals; no allocation allowed) ----------------
__device__ int   g_fps_idx[M_PTS];
__device__ int   g_nbr[M_PTS * KNN_K];
__device__ float g_h[N_PTS * COUT];                  // relu(xW+b), 16 MB

// strict non-FMA fp32 distance: matches XLA's mul -> reduce-add lowering (rel_err==0 verified)
__device__ __forceinline__ float dist2s(float x, float y, float z,
                                        float px, float py, float pz) {
    float dx = __fsub_rn(x, px);
    float dy = __fsub_rn(y, py);
    float dz = __fsub_rn(z, pz);
    return __fadd_rn(__fadd_rn(__fmul_rn(dx, dx), __fmul_rn(dy, dy)), __fmul_rn(dz, dz));
}

// ---------------- FPS: persistent 8-CTA cluster, DSMEM slot exchange ----------------
// slot word layout: [63:32] = float bits of min-dist (>=0, order-preserving as unsigned)
//                   [31:17] = 32767 - point_idx  (max-reduce ties -> smaller idx,
//                             matching jnp.argmax first-index semantics)
//                   [13:0]  = iteration tag (it <= 8191 < 16384)
__global__ void __launch_bounds__(FPS_THREADS, 1) __cluster_dims__(FPS_CTAS, 1, 1)
fps_kernel(const float* __restrict__ pos) {
    __shared__ unsigned long long s_slot[2];   // parity double-buffer, polled by cluster peers
    __shared__ unsigned s_val[32];
    __shared__ unsigned s_idx[32];
    __shared__ float s_pick[3];

    const int tid  = threadIdx.x;
    const int warp = tid >> 5, lane = tid & 31;
    const int cta  = blockIdx.x;               // == cluster rank (cluster spans the grid)
    const int gbase = (cta * FPS_THREADS + tid) * FPS_PPT;

    float X[FPS_PPT], Y[FPS_PPT], Z[FPS_PPT], Mn[FPS_PPT];
    #pragma unroll
    for (int p = 0; p < FPS_PPT; ++p) {
        X[p] = pos[(gbase + p) * 3 + 0];
        Y[p] = pos[(gbase + p) * 3 + 1];
        Z[p] = pos[(gbase + p) * 3 + 2];
        Mn[p] = __int_as_float(0x7f800000);    // +inf
    }

    if (tid == 0) { s_slot[0] = 0ull; s_slot[1] = 0ull; }

    // DSMEM addresses of the 8 peer slots (lane r of warp0 polls rank r)
    const uint32_t slot_laddr = (uint32_t)__cvta_generic_to_shared(&s_slot[0]);
    uint32_t peer_addr = 0;
    if (warp == 0 && lane < FPS_CTAS) {
        asm("mapa.shared::cluster.u32 %0, %1, %2;"
            : "=r"(peer_addr) : "r"(slot_laddr), "r"(lane));
    }

    float px = pos[0], py = pos[1], pz = pos[2];   // first pick = index 0
    if (cta == 0 && tid == 0) g_fps_idx[0] = 0;

    // all peers' slots must be zeroed before anyone writes round-1 values
    asm volatile("barrier.cluster.arrive.aligned;" ::: "memory");
    asm volatile("barrier.cluster.wait.aligned;"   ::: "memory");

    for (int it = 1; it < M_PTS; ++it) {
        // update register-resident min-dists (min is exact; order-independent)
        #pragma unroll
        for (int p = 0; p < FPS_PPT; ++p)
            Mn[p] = fminf(Mn[p], dist2s(X[p], Y[p], Z[p], px, py, pz));

        // thread-local argmax, first-index tie-break (strict > keeps smaller idx)
        float bv = Mn[0]; unsigned bi = (unsigned)gbase;
        #pragma unroll
        for (int p = 1; p < FPS_PPT; ++p)
            if (Mn[p] > bv) { bv = Mn[p]; bi = (unsigned)(gbase + p); }

        // warp stage: REDUX max-val then min-idx among matches
        unsigned vb   = __float_as_uint(bv);
        unsigned wmax = __reduce_max_sync(0xffffffffu, vb);
        unsigned widx = __reduce_min_sync(0xffffffffu, (vb == wmax) ? bi : 0xffffffffu);
        if (lane == 0) { s_val[warp] = wmax; s_idx[warp] = widx; }
        __syncthreads();

        if (warp == 0) {
            // CTA stage over the 32 warp winners
            unsigned v    = s_val[lane], ix = s_idx[lane];
            unsigned cmax = __reduce_max_sync(0xffffffffu, v);
            unsigned cidx = __reduce_min_sync(0xffffffffu, (v == cmax) ? ix : 0xffffffffu);

            const unsigned tag = (unsigned)it;      // < 16384
            const int par = it & 1;
            if (lane == 0) {
                unsigned long long key = ((unsigned long long)cmax << 32)
                                       | ((unsigned long long)(32767u - cidx) << 17)
                                       | (unsigned long long)tag;
                asm volatile("st.relaxed.cluster.shared::cta.b64 [%0], %1;"
                             :: "r"(slot_laddr + (uint32_t)(par * 8)), "l"(key) : "memory");
            }

            // poll all 8 peers' slots via DSMEM (tag in same word -> no fence needed)
            unsigned long long v64 = 0ull;
            if (lane < FPS_CTAS) {
                const uint32_t pa = peer_addr + (uint32_t)(par * 8);
                do {
                    asm volatile("ld.relaxed.cluster.shared::cluster.b64 %0, [%1];"
                                 : "=l"(v64) : "r"(pa) : "memory");
                } while ((unsigned)(v64 & 0x3FFFull) != tag);
            }
            unsigned hval = (lane < FPS_CTAS) ? (unsigned)(v64 >> 32) : 0u;
            unsigned hmax = __reduce_max_sync(0xffffffffu, hval);
            unsigned hinv = __reduce_max_sync(0xffffffffu,
                                (lane < FPS_CTAS && hval == hmax)
                                    ? (unsigned)((v64 >> 17) & 0x7FFFull) : 0u);
            if (lane == 0) {
                int idx = 32767 - (int)hinv;
                if (cta == 0) g_fps_idx[it] = idx;
                s_pick[0] = pos[idx * 3 + 0];
                s_pick[1] = pos[idx * 3 + 1];
                s_pick[2] = pos[idx * 3 + 2];
            }
        }
        __syncthreads();
        px = s_pick[0]; py = s_pick[1]; pz = s_pick[2];
    }

    // no CTA may exit while peers might still read its smem slots
    asm volatile("barrier.cluster.arrive.aligned;" ::: "memory");
    asm volatile("barrier.cluster.wait.aligned;"   ::: "memory");
}

// ---------------- KNN: warp per query, smem-chunked candidate points ----------------
#define KNN_THREADS 256
#define KNN_CHUNK   4096   // 4096 * 3 * 4B = 48 KB smem

__global__ void __launch_bounds__(KNN_THREADS) knn_kernel(const float* __restrict__ pos) {
    __shared__ float s_pos[KNN_CHUNK * 3];
    const int tid  = threadIdx.x;
    const int warp = tid >> 5, lane = tid & 31;
    const int m    = blockIdx.x * (KNN_THREADS / 32) + warp;

    const int qidx = g_fps_idx[m];
    const float qx = pos[qidx * 3 + 0];
    const float qy = pos[qidx * 3 + 1];
    const float qz = pos[qidx * 3 + 2];

    unsigned long long bk[KNN_K];
    #pragma unroll
    for (int i = 0; i < KNN_K; ++i) bk[i] = 0xFFFFFFFFFFFFFFFFull;
    unsigned long long worst = 0xFFFFFFFFFFFFFFFFull;
    int ws = 0;

    for (int base = 0; base < N_PTS; base += KNN_CHUNK) {
        __syncthreads();
        for (int i = tid; i < KNN_CHUNK * 3; i += KNN_THREADS)
            s_pos[i] = pos[base * 3 + i];
        __syncthreads();

        for (int j = lane; j < KNN_CHUNK; j += 32) {
            float d = dist2s(qx, qy, qz, s_pos[j * 3], s_pos[j * 3 + 1], s_pos[j * 3 + 2]);
            unsigned long long key = ((unsigned long long)__float_as_uint(d) << 32)
                                   | (unsigned int)(base + j);
            if (key < worst) {          // lexicographic (d, idx): matches stable top_k
                bk[ws] = key;
                worst = 0ull;
                #pragma unroll
                for (int i = 0; i < KNN_K; ++i)
                    if (bk[i] > worst) { worst = bk[i]; ws = i; }
            }
        }
    }

    // merge 32 lanes' top-16 -> global top-16 (keys are unique: idx in low bits)
    for (int r = 0; r < KNN_K; ++r) {
        unsigned long long lm = 0xFFFFFFFFFFFFFFFFull;
        #pragma unroll
        for (int i = 0; i < KNN_K; ++i) if (bk[i] < lm) lm = bk[i];
        unsigned long long w = lm;
        #pragma unroll
        for (int off = 16; off > 0; off >>= 1) {
            unsigned long long o = __shfl_xor_sync(0xffffffffu, w, off);
            if (o < w) w = o;
        }
        if (lane == 0) g_nbr[m * KNN_K + r] = (int)(w & 0xFFFFFFFFull);
        if (lm == w) {
            bool rm = false;
            #pragma unroll
            for (int i = 0; i < KNN_K; ++i)
                if (!rm && bk[i] == w) { bk[i] = 0xFFFFFFFFFFFFFFFFull; rm = true; }
        }
    }
}

// ---------------- MLP: h = relu(x @ W + b), smem-tiled fp32 ----------------
#define GEMM_THREADS 256
#define GEMM_ROWS    16

__global__ void __launch_bounds__(GEMM_THREADS) mlp_kernel(const float* __restrict__ x,
                                                           const float* __restrict__ W,
                                                           const float* __restrict__ b) {
    __shared__ float sW[CIN * COUT];        // 32 KB
    __shared__ float sx[GEMM_ROWS * CIN];   // 4 KB
    const int tid  = threadIdx.x;
    const int row0 = blockIdx.x * GEMM_ROWS;

    for (int i = tid; i < CIN * COUT; i += GEMM_THREADS) sW[i] = W[i];
    for (int i = tid; i < GEMM_ROWS * CIN; i += GEMM_THREADS) sx[i] = x[row0 * CIN + i];
    __syncthreads();

    const int c  = tid & (COUT - 1);
    const int rg = tid >> 7;   // 0 or 1 -> rows rg*8 .. rg*8+7
    float acc[8];
    #pragma unroll
    for (int r = 0; r < 8; ++r) acc[r] = 0.f;

    for (int k = 0; k < CIN; ++k) {
        float wv = sW[k * COUT + c];
        #pragma unroll
        for (int r = 0; r < 8; ++r)
            acc[r] = fmaf(sx[(rg * 8 + r) * CIN + k], wv, acc[r]);
    }
    float bv = b[c];
    #pragma unroll
    for (int r = 0; r < 8; ++r)
        g_h[(row0 + rg * 8 + r) * COUT + c] = fmaxf(acc[r] + bv, 0.f);
}

// ---------------- max over K neighbors ----------------
__global__ void __launch_bounds__(COUT) gather_kernel(float* __restrict__ out) {
    const int m = blockIdx.x;
    const int c = threadIdx.x;
    __shared__ int s_n[KNN_K];
    if (c < KNN_K) s_n[c] = g_nbr[m * KNN_K + c];
    __syncthreads();
    float best = g_h[s_n[0] * COUT + c];
    #pragma unroll
    for (int k = 1; k < KNN_K; ++k)
        best = fmaxf(best, g_h[s_n[k] * COUT + c]);
    out[m * COUT + c] = best;
}

// ---------------- sub_pos + sub_batch outputs ----------------
__global__ void subpos_kernel(const float* __restrict__ pos, float* __restrict__ out) {
    const int m = blockIdx.x * blockDim.x + threadIdx.x;
    if (m < M_PTS) {
        const int idx = g_fps_idx[m];
        float* sp = out + (M_PTS * COUT);            // sub_pos after out
        sp[m * 3 + 0] = pos[idx * 3 + 0];
        sp[m * 3 + 1] = pos[idx * 3 + 1];
        sp[m * 3 + 2] = pos[idx * 3 + 2];
        out[M_PTS * COUT + M_PTS * 3 + m] = 0.0f;    // sub_batch = 0 (bit-identical to int32 0)
    }
}

extern "C" void kernel_launch(void* const* d_in, const int* in_sizes, int n_in,
                              void* d_out, int out_size) {
    const float* x   = (const float*)d_in[0];
    const float* pos = (const float*)d_in[1];
    // d_in[2] = batch (all zeros, unused)
    const float* W   = (const float*)d_in[3];
    const float* b   = (const float*)d_in[4];
    float* out = (float*)d_out;

    mlp_kernel<<<N_PTS / GEMM_ROWS, GEMM_THREADS>>>(x, W, b);
    fps_kernel<<<FPS_CTAS, FPS_THREADS>>>(pos);
    subpos_kernel<<<(M_PTS + 255) / 256, 256>>>(pos, out);
    knn_kernel<<<M_PTS / (KNN_THREADS / 32), KNN_THREADS>>>(pos);
    gather_kernel<<<M_PTS, COUT>>>(out);
}

// round 3
// speedup vs baseline: 3.4200x; 1.0497x over previous
#include <cuda_runtime.h>
#include <cstdint>

#define N_PTS 32768
#define M_PTS 8192
#define CIN   64
#define COUT  128
#define KNN_K 16

#define FPS_CTAS    8
#define FPS_THREADS 1024
#define FPS_PPT     4      // 8*1024*4 = 32768
#define FULLMASK    0xffffffffu

// ---------------- scratch (device globals; no allocation allowed) ----------------
__device__ int   g_fps_idx[M_PTS];
__device__ int   g_nbr[M_PTS * KNN_K];
__device__ float g_h[N_PTS * COUT];      // relu(xW+b), 16 MB
// binning scratch
__device__ int   g_cellcnt[4096];
__device__ int   g_celloff[4096];
__device__ float g_bx[N_PTS], g_by[N_PTS], g_bz[N_PTS];
__device__ int   g_bidx[N_PTS];

// strict non-FMA fp32 distance: matches XLA mul -> reduce-add (rel_err==0 verified R1/R2)
__device__ __forceinline__ float dist2s(float x, float y, float z,
                                        float px, float py, float pz) {
    float dx = __fsub_rn(x, px);
    float dy = __fsub_rn(y, py);
    float dz = __fsub_rn(z, pz);
    return __fadd_rn(__fadd_rn(__fmul_rn(dx, dx), __fmul_rn(dy, dy)), __fmul_rn(dz, dz));
}

// ---------------- binning: 16^3 Morton grid ----------------
__device__ __forceinline__ int expand3(int v) {   // 4 bits -> every 3rd bit
    return (v & 1) | ((v & 2) << 2) | ((v & 4) << 4) | ((v & 8) << 6);
}
__device__ __forceinline__ int cell_of(float x, float y, float z) {
    int cx = min(15, max(0, (int)floorf((x + 4.0f) * 2.0f)));
    int cy = min(15, max(0, (int)floorf((y + 4.0f) * 2.0f)));
    int cz = min(15, max(0, (int)floorf((z + 4.0f) * 2.0f)));
    return expand3(cx) | (expand3(cy) << 1) | (expand3(cz) << 2);
}

__global__ void zero_kernel() {
    int i = blockIdx.x * blockDim.x + threadIdx.x;
    if (i < 4096) g_cellcnt[i] = 0;
}

__global__ void hist_kernel(const float* __restrict__ pos) {
    int i = blockIdx.x * blockDim.x + threadIdx.x;
    if (i < N_PTS)
        atomicAdd(&g_cellcnt[cell_of(pos[i*3], pos[i*3+1], pos[i*3+2])], 1);
}

__global__ void __launch_bounds__(1024) scan_kernel() {
    __shared__ int s_w[32];
    const int tid = threadIdx.x, lane = tid & 31, w = tid >> 5;
    int v0 = g_cellcnt[tid*4+0], v1 = g_cellcnt[tid*4+1];
    int v2 = g_cellcnt[tid*4+2], v3 = g_cellcnt[tid*4+3];
    int local = v0 + v1 + v2 + v3;
    int x = local;
    #pragma unroll
    for (int off = 1; off < 32; off <<= 1) {
        int y = __shfl_up_sync(FULLMASK, x, off);
        if (lane >= off) x += y;
    }
    if (lane == 31) s_w[w] = x;
    __syncthreads();
    if (w == 0) {
        int y = s_w[lane];
        #pragma unroll
        for (int off = 1; off < 32; off <<= 1) {
            int z = __shfl_up_sync(FULLMASK, y, off);
            if (lane >= off) y += z;
        }
        s_w[lane] = y;
    }
    __syncthreads();
    int exc = x - local + (w > 0 ? s_w[w-1] : 0);
    g_celloff[tid*4+0] = exc;
    g_celloff[tid*4+1] = exc + v0;
    g_celloff[tid*4+2] = exc + v0 + v1;
    g_celloff[tid*4+3] = exc + v0 + v1 + v2;
}

__global__ void scatter_kernel(const float* __restrict__ pos) {
    int i = blockIdx.x * blockDim.x + threadIdx.x;
    if (i < N_PTS) {
        float x = pos[i*3], y = pos[i*3+1], z = pos[i*3+2];
        int slot = atomicAdd(&g_celloff[cell_of(x, y, z)], 1);
        g_bx[slot] = x; g_by[slot] = y; g_bz[slot] = z; g_bidx[slot] = i;
    }
}

// ---------------- FPS: 8-CTA cluster, bbox pruning + coord-carrying DSMEM exchange ----
// slot words (8B each, parity-doubled): w0 = (maxmind<<32)|(invidx<<17)|tag
//   w1 = (xbits<<32)|tag   w2 = (ybits<<32)|tag   w3 = (zbits<<32)|tag
__global__ void __launch_bounds__(FPS_THREADS, 1) __cluster_dims__(FPS_CTAS, 1, 1)
fps_kernel(const float* __restrict__ pos) {
    __shared__ unsigned long long s_slot[8];        // [parity][word]
    __shared__ unsigned s_val[32], s_idx[32];
    __shared__ float s_wx[32], s_wy[32], s_wz[32];
    __shared__ float s_pick[3];

    const int tid  = threadIdx.x;
    const int warp = tid >> 5, lane = tid & 31;
    const int cta  = blockIdx.x;
    const int wbase = (cta * 32 + warp) * 128;      // this warp's 128 binned points

    float X[FPS_PPT], Y[FPS_PPT], Z[FPS_PPT], Mn[FPS_PPT];
    unsigned I[FPS_PPT];
    #pragma unroll
    for (int p = 0; p < FPS_PPT; ++p) {
        int j = wbase + lane + p * 32;
        X[p] = g_bx[j]; Y[p] = g_by[j]; Z[p] = g_bz[j];
        I[p] = (unsigned)g_bidx[j];
        Mn[p] = __int_as_float(0x7f800000);
    }

    // warp bbox over its 128 points (one-time)
    float bxmin = fminf(fminf(X[0], X[1]), fminf(X[2], X[3]));
    float bxmax = fmaxf(fmaxf(X[0], X[1]), fmaxf(X[2], X[3]));
    float bymin = fminf(fminf(Y[0], Y[1]), fminf(Y[2], Y[3]));
    float bymax = fmaxf(fmaxf(Y[0], Y[1]), fmaxf(Y[2], Y[3]));
    float bzmin = fminf(fminf(Z[0], Z[1]), fminf(Z[2], Z[3]));
    float bzmax = fmaxf(fmaxf(Z[0], Z[1]), fmaxf(Z[2], Z[3]));
    #pragma unroll
    for (int off = 16; off > 0; off >>= 1) {
        bxmin = fminf(bxmin, __shfl_xor_sync(FULLMASK, bxmin, off));
        bxmax = fmaxf(bxmax, __shfl_xor_sync(FULLMASK, bxmax, off));
        bymin = fminf(bymin, __shfl_xor_sync(FULLMASK, bymin, off));
        bymax = fmaxf(bymax, __shfl_xor_sync(FULLMASK, bymax, off));
        bzmin = fminf(bzmin, __shfl_xor_sync(FULLMASK, bzmin, off));
        bzmax = fmaxf(bzmax, __shfl_xor_sync(FULLMASK, bzmax, off));
    }

    float wval = __int_as_float(0x7f800000);   // cached warp max-mind (skip threshold)

    if (tid < 8) s_slot[tid] = 0ull;

    // DSMEM peer word addresses: lane polls word (lane&3) of peer (lane>>2)
    const uint32_t slot_laddr = (uint32_t)__cvta_generic_to_shared(&s_slot[0]);
    uint32_t peer_base = 0;
    if (warp == 0) {
        asm("mapa.shared::cluster.u32 %0, %1, %2;"
            : "=r"(peer_base) : "r"(slot_laddr), "r"(lane >> 2));
    }

    float px = pos[0], py = pos[1], pz = pos[2];   // first pick = index 0
    if (cta == 0 && tid == 0) g_fps_idx[0] = 0;

    asm volatile("barrier.cluster.arrive.aligned;" ::: "memory");
    asm volatile("barrier.cluster.wait.aligned;"   ::: "memory");

    for (int it = 1; it < M_PTS; ++it) {
        // exact-safe lower bound: rn rounding is monotone, so d_lb <= every lane's fp dist
        float dxl = fmaxf(0.f, fmaxf(__fsub_rn(bxmin, px), __fsub_rn(px, bxmax)));
        float dyl = fmaxf(0.f, fmaxf(__fsub_rn(bymin, py), __fsub_rn(py, bymax)));
        float dzl = fmaxf(0.f, fmaxf(__fsub_rn(bzmin, pz), __fsub_rn(pz, bzmax)));
        float dlb = __fadd_rn(__fadd_rn(__fmul_rn(dxl, dxl), __fmul_rn(dyl, dyl)),
                              __fmul_rn(dzl, dzl));

        if (dlb < wval) {                      // warp-uniform branch
            #pragma unroll
            for (int p = 0; p < FPS_PPT; ++p)
                Mn[p] = fminf(Mn[p], dist2s(X[p], Y[p], Z[p], px, py, pz));

            // thread-local argmax, min-orig-idx tie-break
            float bv = Mn[0]; unsigned bi = I[0];
            float bx = X[0], by = Y[0], bz = Z[0];
            #pragma unroll
            for (int p = 1; p < FPS_PPT; ++p) {
                if (Mn[p] > bv || (Mn[p] == bv && I[p] < bi)) {
                    bv = Mn[p]; bi = I[p]; bx = X[p]; by = Y[p]; bz = Z[p];
                }
            }
            unsigned vb   = __float_as_uint(bv);
            unsigned wmax = __reduce_max_sync(FULLMASK, vb);
            unsigned widx = __reduce_min_sync(FULLMASK, (vb == wmax) ? bi : 0xffffffffu);
            wval = __uint_as_float(wmax);
            if (vb == wmax && bi == widx) {    // unique winner lane stores candidate
                s_val[warp] = wmax; s_idx[warp] = widx;
                s_wx[warp] = bx; s_wy[warp] = by; s_wz[warp] = bz;
            }
        }
        // else: cached smem candidate from last update round is still exact
        __syncthreads();

        if (warp == 0) {
            unsigned v  = s_val[lane], ix = s_idx[lane];
            float xw = s_wx[lane], yw = s_wy[lane], zw = s_wz[lane];
            unsigned cmax = __reduce_max_sync(FULLMASK, v);
            unsigned cidx = __reduce_min_sync(FULLMASK, (v == cmax) ? ix : 0xffffffffu);
            int wl = __ffs(__ballot_sync(FULLMASK, v == cmax && ix == cidx)) - 1;
            float cx = __shfl_sync(FULLMASK, xw, wl);
            float cy = __shfl_sync(FULLMASK, yw, wl);
            float cz = __shfl_sync(FULLMASK, zw, wl);

            const unsigned tag = (unsigned)it;          // < 16384
            const int par = it & 1;
            if (lane == 0) {
                unsigned long long k0 = ((unsigned long long)cmax << 32)
                                      | ((unsigned long long)(32767u - cidx) << 17)
                                      | (unsigned long long)tag;
                unsigned long long k1 = ((unsigned long long)__float_as_uint(cx) << 32) | tag;
                unsigned long long k2 = ((unsigned long long)__float_as_uint(cy) << 32) | tag;
                unsigned long long k3 = ((unsigned long long)__float_as_uint(cz) << 32) | tag;
                uint32_t a = slot_laddr + (uint32_t)(par * 32);
                asm volatile("st.relaxed.cluster.shared::cta.b64 [%0], %1;" :: "r"(a),      "l"(k0) : "memory");
                asm volatile("st.relaxed.cluster.shared::cta.b64 [%0], %1;" :: "r"(a + 8),  "l"(k1) : "memory");
                asm volatile("st.relaxed.cluster.shared::cta.b64 [%0], %1;" :: "r"(a + 16), "l"(k2) : "memory");
                asm volatile("st.relaxed.cluster.shared::cta.b64 [%0], %1;" :: "r"(a + 24), "l"(k3) : "memory");
            }

            // poll: lane polls word (lane&3) of peer (lane>>2); every word self-tagged
            const uint32_t pa = peer_base + (uint32_t)(par * 32 + (lane & 3) * 8);
            unsigned long long v64;
            do {
                asm volatile("ld.relaxed.cluster.shared::cluster.b64 %0, [%1];"
                             : "=l"(v64) : "r"(pa) : "memory");
            } while ((unsigned)(v64 & 0x3FFFull) != tag);

            const bool iskey = (lane & 3) == 0;
            unsigned hval = iskey ? (unsigned)(v64 >> 32) : 0u;
            unsigned hmax = __reduce_max_sync(FULLMASK, hval);
            unsigned hinv = __reduce_max_sync(FULLMASK,
                                (iskey && hval == hmax)
                                    ? (unsigned)((v64 >> 17) & 0x7FFFull) : 0u);
            int l0 = __ffs(__ballot_sync(FULLMASK,
                        iskey && hval == hmax
                        && (unsigned)((v64 >> 17) & 0x7FFFull) == hinv)) - 1;
            unsigned hi32 = (unsigned)(v64 >> 32);
            float pkx = __uint_as_float(__shfl_sync(FULLMASK, hi32, l0 + 1));
            float pky = __uint_as_float(__shfl_sync(FULLMASK, hi32, l0 + 2));
            float pkz = __uint_as_float(__shfl_sync(FULLMASK, hi32, l0 + 3));
            if (lane == 0) {
                s_pick[0] = pkx; s_pick[1] = pky; s_pick[2] = pkz;
                if (cta == 0) g_fps_idx[it] = 32767 - (int)hinv;
            }
        }
        __syncthreads();
        px = s_pick[0]; py = s_pick[1]; pz = s_pick[2];
    }

    asm volatile("barrier.cluster.arrive.aligned;" ::: "memory");
    asm volatile("barrier.cluster.wait.aligned;"   ::: "memory");
}

// ---------------- KNN: warp per query, smem-chunked candidate points ----------------
#define KNN_THREADS 256
#define KNN_CHUNK   4096

__global__ void __launch_bounds__(KNN_THREADS) knn_kernel(const float* __restrict__ pos) {
    __shared__ float s_pos[KNN_CHUNK * 3];
    const int tid  = threadIdx.x;
    const int warp = tid >> 5, lane = tid & 31;
    const int m    = blockIdx.x * (KNN_THREADS / 32) + warp;

    const int qidx = g_fps_idx[m];
    const float qx = pos[qidx * 3 + 0];
    const float qy = pos[qidx * 3 + 1];
    const float qz = pos[qidx * 3 + 2];

    unsigned long long bk[KNN_K];
    #pragma unroll
    for (int i = 0; i < KNN_K; ++i) bk[i] = 0xFFFFFFFFFFFFFFFFull;
    unsigned long long worst = 0xFFFFFFFFFFFFFFFFull;
    int ws = 0;

    for (int base = 0; base < N_PTS; base += KNN_CHUNK) {
        __syncthreads();
        for (int i = tid; i < KNN_CHUNK * 3; i += KNN_THREADS)
            s_pos[i] = pos[base * 3 + i];
        __syncthreads();

        for (int j = lane; j < KNN_CHUNK; j += 32) {
            float d = dist2s(qx, qy, qz, s_pos[j * 3], s_pos[j * 3 + 1], s_pos[j * 3 + 2]);
            unsigned long long key = ((unsigned long long)__float_as_uint(d) << 32)
                                   | (unsigned int)(base + j);
            if (key < worst) {
                bk[ws] = key;
                worst = 0ull;
                #pragma unroll
                for (int i = 0; i < KNN_K; ++i)
                    if (bk[i] > worst) { worst = bk[i]; ws = i; }
            }
        }
    }

    for (int r = 0; r < KNN_K; ++r) {
        unsigned long long lm = 0xFFFFFFFFFFFFFFFFull;
        #pragma unroll
        for (int i = 0; i < KNN_K; ++i) if (bk[i] < lm) lm = bk[i];
        unsigned long long w = lm;
        #pragma unroll
        for (int off = 16; off > 0; off >>= 1) {
            unsigned long long o = __shfl_xor_sync(FULLMASK, w, off);
            if (o < w) w = o;
        }
        if (lane == 0) g_nbr[m * KNN_K + r] = (int)(w & 0xFFFFFFFFull);
        if (lm == w) {
            bool rm = false;
            #pragma unroll
            for (int i = 0; i < KNN_K; ++i)
                if (!rm && bk[i] == w) { bk[i] = 0xFFFFFFFFFFFFFFFFull; rm = true; }
        }
    }
}

// ---------------- MLP: h = relu(x @ W + b) ----------------
#define GEMM_THREADS 256
#define GEMM_ROWS    16

__global__ void __launch_bounds__(GEMM_THREADS) mlp_kernel(const float* __restrict__ x,
                                                           const float* __restrict__ W,
                                                           const float* __restrict__ b) {
    __shared__ float sW[CIN * COUT];
    __shared__ float sx[GEMM_ROWS * CIN];
    const int tid  = threadIdx.x;
    const int row0 = blockIdx.x * GEMM_ROWS;

    for (int i = tid; i < CIN * COUT; i += GEMM_THREADS) sW[i] = W[i];
    for (int i = tid; i < GEMM_ROWS * CIN; i += GEMM_THREADS) sx[i] = x[row0 * CIN + i];
    __syncthreads();

    const int c  = tid & (COUT - 1);
    const int rg = tid >> 7;
    float acc[8];
    #pragma unroll
    for (int r = 0; r < 8; ++r) acc[r] = 0.f;

    for (int k = 0; k < CIN; ++k) {
        float wv = sW[k * COUT + c];
        #pragma unroll
        for (int r = 0; r < 8; ++r)
            acc[r] = fmaf(sx[(rg * 8 + r) * CIN + k], wv, acc[r]);
    }
    float bv = b[c];
    #pragma unroll
    for (int r = 0; r < 8; ++r)
        g_h[(row0 + rg * 8 + r) * COUT + c] = fmaxf(acc[r] + bv, 0.f);
}

// ---------------- max over K neighbors ----------------
__global__ void __launch_bounds__(COUT) gather_kernel(float* __restrict__ out) {
    const int m = blockIdx.x;
    const int c = threadIdx.x;
    __shared__ int s_n[KNN_K];
    if (c < KNN_K) s_n[c] = g_nbr[m * KNN_K + c];
    __syncthreads();
    float best = g_h[s_n[0] * COUT + c];
    #pragma unroll
    for (int k = 1; k < KNN_K; ++k)
        best = fmaxf(best, g_h[s_n[k] * COUT + c]);
    out[m * COUT + c] = best;
}

// ---------------- sub_pos + sub_batch ----------------
__global__ void subpos_kernel(const float* __restrict__ pos, float* __restrict__ out) {
    const int m = blockIdx.x * blockDim.x + threadIdx.x;
    if (m < M_PTS) {
        const int idx = g_fps_idx[m];
        float* sp = out + (M_PTS * COUT);
        sp[m * 3 + 0] = pos[idx * 3 + 0];
        sp[m * 3 + 1] = pos[idx * 3 + 1];
        sp[m * 3 + 2] = pos[idx * 3 + 2];
        out[M_PTS * COUT + M_PTS * 3 + m] = 0.0f;   // sub_batch = 0
    }
}

extern "C" void kernel_launch(void* const* d_in, const int* in_sizes, int n_in,
                              void* d_out, int out_size) {
    const float* x   = (const float*)d_in[0];
    const float* pos = (const float*)d_in[1];
    const float* W   = (const float*)d_in[3];
    const float* b   = (const float*)d_in[4];
    float* out = (float*)d_out;

    zero_kernel<<<4, 1024>>>();
    hist_kernel<<<32, 1024>>>(pos);
    scan_kernel<<<1, 1024>>>();
    scatter_kernel<<<32, 1024>>>(pos);
    fps_kernel<<<FPS_CTAS, FPS_THREADS>>>(pos);
    mlp_kernel<<<N_PTS / GEMM_ROWS, GEMM_THREADS>>>(x, W, b);
    subpos_kernel<<<(M_PTS + 255) / 256, 256>>>(pos, out);
    knn_kernel<<<M_PTS / (KNN_THREADS / 32), KNN_THREADS>>>(pos);
    gather_kernel<<<M_PTS, COUT>>>(out);
}